// round 15
// baseline (speedup 1.0000x reference)
#include <cuda_runtime.h>
#include <cuda_fp16.h>
#include <cstdint>

// out[b] = x_b^T Q x_b, B=131072, F=512, fp32, Q upper-triangular (incl diag).
// fp16 HMMA. CTA tile 64x128, 256 threads, 8 warps = wk(2) x wm(2) x wn(2),
// warp tile 32x64 over half the k-steps. B pre-baked in mma register-fragment
// layout, fetched with __ldg from the L2-hot 320KB array and SOFTWARE-
// PIPELINED in registers (rotating 16-reg buffers: next half-tile's loads
// issue before the current half-tile's MMA block) => near-zero exposed L2
// latency. No smem B, no mbarriers, no main-loop sync. Triangular walk fully
// unrolled; diagonal half-chunks skip the all-zero wn=0 MMAs. 66.5KB smem =>
// 2 CTAs/SM.

#define F_DIM 512
#define BM 64
#define BN 128
#define KC 64
#define NTHREADS 256
#define NIT 20

// B fragments: [tile t][frag fidx=(kk*2+wn)*4+X][lane] -> uint4 {b0,b1,b2,b3}
__device__ uint4 g_Bfrag[NIT * 32 * 32];   // 320KB, L2-resident

__device__ __constant__ int TN[NIT] = {0,0,1,1,1,1,2,2,2,2,2,2,3,3,3,3,3,3,3,3};
__device__ __constant__ int TC[NIT] = {0,1,0,1,2,3,0,1,2,3,4,5,0,1,2,3,4,5,6,7};

// smem layout
#define SM_A     0                 // 64 rows x 1024B = 64KB
#define SM_RED   65536             // 4 x 64 floats = 1KB
#define SM_TOTAL 66560             // x2 CTAs fits

__device__ __forceinline__ uint32_t smem_u32(const void* p) {
    uint32_t a;
    asm("{ .reg .u64 t; cvta.to.shared.u64 t, %1; cvt.u32.u64 %0, t; }" : "=r"(a) : "l"(p));
    return a;
}
__device__ __forceinline__ void ldsm4(uint32_t r[4], uint32_t addr) {
    asm volatile("ldmatrix.sync.aligned.m8n8.x4.shared.b16 {%0,%1,%2,%3}, [%4];"
                 : "=r"(r[0]), "=r"(r[1]), "=r"(r[2]), "=r"(r[3]) : "r"(addr));
}
__device__ __forceinline__ void mma_fp16(float d[4], const uint32_t a[4],
                                         uint32_t b0, uint32_t b1) {
    asm volatile(
        "mma.sync.aligned.m16n8k16.row.col.f32.f16.f16.f32 "
        "{%0,%1,%2,%3}, {%4,%5,%6,%7}, {%8,%9}, {%0,%1,%2,%3};"
        : "+f"(d[0]), "+f"(d[1]), "+f"(d[2]), "+f"(d[3])
        : "r"(a[0]), "r"(a[1]), "r"(a[2]), "r"(a[3]), "r"(b0), "r"(b1));
}
__device__ __forceinline__ uint32_t packh2(float lo, float hi) {
    union { __half2 h; uint32_t u; } cvt;
    cvt.h = __floats2half2_rn(lo, hi);
    return cvt.u;
}

// ---- prep: bake B fragments in mma register layout (same as R14) ----
__global__ void prep_frags_kernel(const float* __restrict__ Q) {
    int i = blockIdx.x * blockDim.x + threadIdx.x;   // 0 .. NIT*1024-1
    int t    = i >> 10;
    int fidx = (i >> 5) & 31;
    int l    = i & 31;
    int kk = fidx >> 3, wn = (fidx >> 2) & 1, X = fidx & 3;
    int n = TN[t], c = TC[t];
    int n0 = wn * 64 + X * 16 + (l >> 2);
    int k0 = kk * 16 + 2 * (l & 3);
    const float* Qb = Q + (size_t)(c * KC) * F_DIM + n * BN;
    #define QV(dk, dg) Qb[(size_t)(k0 + (dk)) * F_DIM + n0 + (dg)]
    uint4 v;
    v.x = packh2(QV(0, 0), QV(1, 0));
    v.y = packh2(QV(0, 8), QV(1, 8));
    v.z = packh2(QV(8, 0), QV(9, 0));
    v.w = packh2(QV(8, 8), QV(9, 8));
    #undef QV
    g_Bfrag[(t * 32 + fidx) * 32 + l] = v;
}

// ---- main kernel ----
__global__ __launch_bounds__(NTHREADS, 2)
void bilinear_fp16_kernel(const float* __restrict__ x, float* __restrict__ out) {
    extern __shared__ __align__(1024) char smem[];
    const uint32_t sbase = smem_u32(smem);
    const int tid  = threadIdx.x;
    const int lane = tid & 31;
    const int wid  = tid >> 5;
    const int wk   = wid & 1;         // k-step half within each chunk
    const int wm   = (wid >> 1) & 1;  // 32-row strip
    const int wn   = wid >> 2;        // 64-col half
    const int r0   = blockIdx.x * BM;

    // ---- prologue: convert full X row-block [64 x 512] fp32 -> fp16 into A ----
    #pragma unroll
    for (int it = 0; it < 16; ++it) {
        int v   = it * NTHREADS + tid;
        int row = v >> 6;                 // 0..63
        int k   = (v & 63) * 8;           // 0..504
        const float* xp = &x[(size_t)(r0 + row) * F_DIM + k];
        float4 t0 = *reinterpret_cast<const float4*>(xp);
        float4 t1 = *reinterpret_cast<const float4*>(xp + 4);
        uint4 u;
        u.x = packh2(t0.x, t0.y);
        u.y = packh2(t0.z, t0.w);
        u.z = packh2(t1.x, t1.y);
        u.w = packh2(t1.z, t1.w);
        uint32_t off = row * 1024 + (((uint32_t)k * 2) ^ ((row & 7) * 16));
        *reinterpret_cast<uint4*>(smem + SM_A + off) = u;
    }
    __syncthreads();   // the ONLY main-path synchronization

    // ---- ldmatrix address components for A ----
    const uint32_t lane_swz = (lane & 7) * 16;
    uint32_t a_base[2];
    #pragma unroll
    for (int j = 0; j < 2; ++j)
        a_base[j] = sbase + SM_A + (wm * 32 + j * 16 + (lane & 15)) * 1024;
    const uint32_t a_seg = (lane >> 4) * 16;

    // B fragment base pointer for this warp's (wk, wn, lane).
    // Frag (tile t, kk2, X) lives at bfw + ((t*32) + kk2*8 + X)*32.
    const uint4* bfw = g_Bfrag + (uint32_t)((wk * 16 + wn * 4) * 32 + lane);
    #define BOFF(t, kk2, X) ((uint32_t)((t) * 32 + (kk2) * 8 + (X)) * 32)

    float d[2][8][4];
    #pragma unroll
    for (int mf = 0; mf < 2; ++mf)
        #pragma unroll
        for (int nj = 0; nj < 8; ++nj)
            #pragma unroll
            for (int q = 0; q < 4; ++q) d[mf][nj][q] = 0.f;

    float acc[2][2];
    acc[0][0] = acc[0][1] = acc[1][0] = acc[1][1] = 0.f;

    const int ep_r  = lane >> 2;
    const int ep_c2 = (lane & 3) * 2;

    // pipeline preload: tile 0, kk2=0 fragments
    uint4 P[4];
    #pragma unroll
    for (int X = 0; X < 4; ++X) P[X] = __ldg(bfw + BOFF(0, 0, X));

    int t = 0;
    #pragma unroll
    for (int n = 0; n < 4; ++n) {
        #pragma unroll
        for (int c = 0; c <= 2 * n + 1; ++c, ++t) {
            const bool lastc = (c == 2 * n + 1);
            const bool skip  = lastc && (wn == 0);   // all-zero B columns

            // issue kk2=1 loads for this tile (consumed after kk2=0 MMAs)
            uint4 C1[4];
            #pragma unroll
            for (int X = 0; X < 4; ++X) C1[X] = __ldg(bfw + BOFF(t, 1, X));

            // ---- kk2 = 0 block: consumes P (already in flight/ready) ----
            if (!skip) {
                const uint32_t akb = (uint32_t)(c * 128 + wk * 64) + a_seg;
                uint32_t a[2][4];
                #pragma unroll
                for (int j = 0; j < 2; ++j)
                    ldsm4(a[j], a_base[j] + (akb ^ lane_swz));
                #pragma unroll
                for (int X = 0; X < 4; ++X) {
                    mma_fp16(d[0][X * 2 + 0], a[0], P[X].x, P[X].z);
                    mma_fp16(d[0][X * 2 + 1], a[0], P[X].y, P[X].w);
                    mma_fp16(d[1][X * 2 + 0], a[1], P[X].x, P[X].z);
                    mma_fp16(d[1][X * 2 + 1], a[1], P[X].y, P[X].w);
                }
            }

            // issue next tile's kk2=0 loads (consumed next iteration)
            uint4 Pn[4];
            if (t + 1 < NIT) {
                #pragma unroll
                for (int X = 0; X < 4; ++X) Pn[X] = __ldg(bfw + BOFF(t + 1, 0, X));
            }

            // ---- kk2 = 1 block: consumes C1 ----
            if (!skip) {
                const uint32_t akb = (uint32_t)(c * 128 + wk * 64 + 32) + a_seg;
                uint32_t a[2][4];
                #pragma unroll
                for (int j = 0; j < 2; ++j)
                    ldsm4(a[j], a_base[j] + (akb ^ lane_swz));
                #pragma unroll
                for (int X = 0; X < 4; ++X) {
                    mma_fp16(d[0][X * 2 + 0], a[0], C1[X].x, C1[X].z);
                    mma_fp16(d[0][X * 2 + 1], a[0], C1[X].y, C1[X].w);
                    mma_fp16(d[1][X * 2 + 0], a[1], C1[X].x, C1[X].z);
                    mma_fp16(d[1][X * 2 + 1], a[1], C1[X].y, C1[X].w);
                }
            }

            // ---- epilogue when this g-tile's k-loop finishes: x from smem ----
            if (lastc) {
                #pragma unroll
                for (int mf = 0; mf < 2; ++mf) {
                    #pragma unroll
                    for (int rg = 0; rg < 2; ++rg) {
                        const int row = wm * 32 + mf * 16 + rg * 8 + ep_r;
                        const uint32_t rbase = (uint32_t)(row * 1024);
                        const uint32_t rswz  = (row & 7) * 16;
                        float sum = 0.f;
                        #pragma unroll
                        for (int nj = 0; nj < 8; ++nj) {
                            const int col = n * BN + wn * 64 + nj * 8 + ep_c2;
                            uint32_t off = rbase + (((uint32_t)col * 2) ^ rswz);
                            __half2 xh = *reinterpret_cast<const __half2*>(
                                smem + SM_A + off);
                            float2 xf = __half22float2(xh);
                            sum += d[mf][nj][rg * 2 + 0] * xf.x +
                                   d[mf][nj][rg * 2 + 1] * xf.y;
                            d[mf][nj][rg * 2 + 0] = 0.f;
                            d[mf][nj][rg * 2 + 1] = 0.f;
                        }
                        acc[mf][rg] += sum;
                    }
                }
            }

            // rotate pipeline buffer
            if (t + 1 < NIT) {
                #pragma unroll
                for (int X = 0; X < 4; ++X) P[X] = Pn[X];
            }
        }
    }

    // ---- reduce: quad lanes, then across the wk x wn warp groups via smem ----
    #pragma unroll
    for (int mf = 0; mf < 2; ++mf)
        #pragma unroll
        for (int rg = 0; rg < 2; ++rg) {
            acc[mf][rg] += __shfl_xor_sync(0xffffffffu, acc[mf][rg], 1);
            acc[mf][rg] += __shfl_xor_sync(0xffffffffu, acc[mf][rg], 2);
        }

    float* red = reinterpret_cast<float*>(smem + SM_RED);
    if ((lane & 3) == 0) {
        const int grp = wk * 2 + wn;   // 0..3
        #pragma unroll
        for (int mf = 0; mf < 2; ++mf)
            #pragma unroll
            for (int rg = 0; rg < 2; ++rg) {
                const int row = wm * 32 + mf * 16 + rg * 8 + ep_r;
                red[grp * BM + row] = acc[mf][rg];
            }
    }
    __syncthreads();
    if (tid < BM)
        out[r0 + tid] = red[tid] + red[BM + tid] +
                        red[2 * BM + tid] + red[3 * BM + tid];
}

extern "C" void kernel_launch(void* const* d_in, const int* in_sizes, int n_in,
                              void* d_out, int out_size) {
    const float* x = (const float*)d_in[0];
    const float* Q = (const float*)d_in[1];
    float* out     = (float*)d_out;

    const int B = in_sizes[0] / F_DIM;

    cudaFuncSetAttribute(bilinear_fp16_kernel,
                         cudaFuncAttributeMaxDynamicSharedMemorySize, SM_TOTAL);

    prep_frags_kernel<<<(NIT * 1024) / 256, 256>>>(Q);
    bilinear_fp16_kernel<<<B / BM, NTHREADS, SM_TOTAL>>>(x, out);
}

// round 16
// speedup vs baseline: 1.0008x; 1.0008x over previous
#include <cuda_runtime.h>
#include <cuda_fp16.h>
#include <cstdint>

// out[b] = x_b^T Q x_b, B=131072, F=512, fp32, Q upper-triangular (incl diag).
// fp16 HMMA. CTA tile 64x128, 256 threads, 8 warps = wm(2) x wn2(4), warp
// tile 32x32 over FULL k (32 accum regs/thread) so regs fit 85 =>
// __launch_bounds__(256,3) => 3 CTAs/SM, 24 warps (RF was the occupancy
// binder at 16). B pre-baked in mma register-fragment layout, fetched
// just-in-time with __ldg from the L2-hot 320KB array. No smem B, no
// mbarriers, no main-loop sync. Triangular walk fully unrolled; diagonal
// half-chunks skip the all-zero wn2<2 MMAs.

#define F_DIM 512
#define BM 64
#define BN 128
#define KC 64
#define NTHREADS 256
#define NIT 20

// B fragments: [tile t][fidx = kk*8 + colblock][lane] -> uint4 {b0,b1,b2,b3}
__device__ uint4 g_Bfrag[NIT * 32 * 32];   // 320KB, L2-resident

__device__ __constant__ int TN[NIT] = {0,0,1,1,1,1,2,2,2,2,2,2,3,3,3,3,3,3,3,3};
__device__ __constant__ int TC[NIT] = {0,1,0,1,2,3,0,1,2,3,4,5,0,1,2,3,4,5,6,7};

// smem layout
#define SM_A     0                 // 64 rows x 1024B = 64KB
#define SM_RED   65536             // 4 x 64 floats = 1KB
#define SM_TOTAL 66560             // x3 CTAs ~= 200KB <= 228KB

__device__ __forceinline__ uint32_t smem_u32(const void* p) {
    uint32_t a;
    asm("{ .reg .u64 t; cvta.to.shared.u64 t, %1; cvt.u32.u64 %0, t; }" : "=r"(a) : "l"(p));
    return a;
}
__device__ __forceinline__ void ldsm4(uint32_t r[4], uint32_t addr) {
    asm volatile("ldmatrix.sync.aligned.m8n8.x4.shared.b16 {%0,%1,%2,%3}, [%4];"
                 : "=r"(r[0]), "=r"(r[1]), "=r"(r[2]), "=r"(r[3]) : "r"(addr));
}
__device__ __forceinline__ void mma_fp16(float d[4], const uint32_t a[4],
                                         uint32_t b0, uint32_t b1) {
    asm volatile(
        "mma.sync.aligned.m16n8k16.row.col.f32.f16.f16.f32 "
        "{%0,%1,%2,%3}, {%4,%5,%6,%7}, {%8,%9}, {%0,%1,%2,%3};"
        : "+f"(d[0]), "+f"(d[1]), "+f"(d[2]), "+f"(d[3])
        : "r"(a[0]), "r"(a[1]), "r"(a[2]), "r"(a[3]), "r"(b0), "r"(b1));
}
__device__ __forceinline__ uint32_t packh2(float lo, float hi) {
    union { __half2 h; uint32_t u; } cvt;
    cvt.h = __floats2half2_rn(lo, hi);
    return cvt.u;
}

// ---- prep: bake B fragments in mma register layout (identical to R14) ----
__global__ void prep_frags_kernel(const float* __restrict__ Q) {
    int i = blockIdx.x * blockDim.x + threadIdx.x;   // 0 .. NIT*1024-1
    int t    = i >> 10;
    int fidx = (i >> 5) & 31;      // kk*8 + cb
    int l    = i & 31;
    int kk = fidx >> 3, cb = fidx & 7;
    int n = TN[t], c = TC[t];
    int n0 = cb * 16 + (l >> 2);
    int k0 = kk * 16 + 2 * (l & 3);
    const float* Qb = Q + (size_t)(c * KC) * F_DIM + n * BN;
    #define QV(dk, dg) Qb[(size_t)(k0 + (dk)) * F_DIM + n0 + (dg)]
    uint4 v;
    v.x = packh2(QV(0, 0), QV(1, 0));
    v.y = packh2(QV(0, 8), QV(1, 8));
    v.z = packh2(QV(8, 0), QV(9, 0));
    v.w = packh2(QV(8, 8), QV(9, 8));
    #undef QV
    g_Bfrag[(t * 32 + fidx) * 32 + l] = v;
}

// ---- main kernel ----
__global__ __launch_bounds__(NTHREADS, 3)
void bilinear_fp16_kernel(const float* __restrict__ x, float* __restrict__ out) {
    extern __shared__ __align__(1024) char smem[];
    const uint32_t sbase = smem_u32(smem);
    const int tid  = threadIdx.x;
    const int lane = tid & 31;
    const int wid  = tid >> 5;
    const int wm   = wid & 1;      // 32-row strip
    const int wn2  = wid >> 1;     // 32-col strip (0..3)
    const int r0   = blockIdx.x * BM;

    // ---- prologue: convert full X row-block [64 x 512] fp32 -> fp16 into A ----
    #pragma unroll
    for (int it = 0; it < 16; ++it) {
        int v   = it * NTHREADS + tid;
        int row = v >> 6;                 // 0..63
        int k   = (v & 63) * 8;           // 0..504
        const float* xp = &x[(size_t)(r0 + row) * F_DIM + k];
        float4 t0 = *reinterpret_cast<const float4*>(xp);
        float4 t1 = *reinterpret_cast<const float4*>(xp + 4);
        uint4 u;
        u.x = packh2(t0.x, t0.y);
        u.y = packh2(t0.z, t0.w);
        u.z = packh2(t1.x, t1.y);
        u.w = packh2(t1.z, t1.w);
        uint32_t off = row * 1024 + (((uint32_t)k * 2) ^ ((row & 7) * 16));
        *reinterpret_cast<uint4*>(smem + SM_A + off) = u;
    }
    __syncthreads();   // the ONLY main-path synchronization

    // ---- ldmatrix address components for A ----
    const uint32_t lane_swz = (lane & 7) * 16;
    uint32_t a_base[2];
    #pragma unroll
    for (int j = 0; j < 2; ++j)
        a_base[j] = sbase + SM_A + (wm * 32 + j * 16 + (lane & 15)) * 1024;
    const uint32_t a_seg = (lane >> 4) * 16;

    // B fragment base pointer: this warp covers col blocks {2*wn2, 2*wn2+1}.
    // Frag (t, kk, cb) at g_Bfrag[(t*32 + kk*8 + cb)*32 + lane].
    const uint4* bfw = g_Bfrag + (uint32_t)(wn2 * 2 * 32 + lane);

    float d[2][4][4];     // [mf][nj][reg] = 32 accumulator regs
    #pragma unroll
    for (int mf = 0; mf < 2; ++mf)
        #pragma unroll
        for (int nj = 0; nj < 4; ++nj)
            #pragma unroll
            for (int q = 0; q < 4; ++q) d[mf][nj][q] = 0.f;

    float acc[2][2];
    acc[0][0] = acc[0][1] = acc[1][0] = acc[1][1] = 0.f;

    const int ep_r  = lane >> 2;
    const int ep_c2 = (lane & 3) * 2;

    int t = 0;
    #pragma unroll
    for (int n = 0; n < 4; ++n) {
        #pragma unroll
        for (int c = 0; c <= 2 * n + 1; ++c, ++t) {
            const bool lastc = (c == 2 * n + 1);
            const bool skip  = lastc && (wn2 < 2);   // all-zero B columns

            if (!skip) {
                #pragma unroll
                for (int kk = 0; kk < 4; ++kk) {
                    const uint32_t akb = (uint32_t)(c * 128 + kk * 32) + a_seg;
                    uint32_t a[2][4];
                    #pragma unroll
                    for (int j = 0; j < 2; ++j)
                        ldsm4(a[j], a_base[j] + (akb ^ lane_swz));

                    const uint32_t bo = (uint32_t)(t * 1024 + kk * 256);
                    uint4 b0 = __ldg(bfw + bo);
                    uint4 b1 = __ldg(bfw + bo + 32);
                    mma_fp16(d[0][0], a[0], b0.x, b0.z);
                    mma_fp16(d[0][1], a[0], b0.y, b0.w);
                    mma_fp16(d[0][2], a[0], b1.x, b1.z);
                    mma_fp16(d[0][3], a[0], b1.y, b1.w);
                    mma_fp16(d[1][0], a[1], b0.x, b0.z);
                    mma_fp16(d[1][1], a[1], b0.y, b0.w);
                    mma_fp16(d[1][2], a[1], b1.x, b1.z);
                    mma_fp16(d[1][3], a[1], b1.y, b1.w);
                }
            }

            // ---- epilogue when this g-tile's k-loop finishes: x from smem ----
            if (lastc) {
                #pragma unroll
                for (int mf = 0; mf < 2; ++mf) {
                    #pragma unroll
                    for (int rg = 0; rg < 2; ++rg) {
                        const int row = wm * 32 + mf * 16 + rg * 8 + ep_r;
                        const uint32_t rbase = (uint32_t)(row * 1024);
                        const uint32_t rswz  = (row & 7) * 16;
                        float sum = 0.f;
                        #pragma unroll
                        for (int nj = 0; nj < 4; ++nj) {
                            const int col = n * BN + wn2 * 32 + nj * 8 + ep_c2;
                            uint32_t off = rbase + (((uint32_t)col * 2) ^ rswz);
                            __half2 xh = *reinterpret_cast<const __half2*>(
                                smem + SM_A + off);
                            float2 xf = __half22float2(xh);
                            sum += d[mf][nj][rg * 2 + 0] * xf.x +
                                   d[mf][nj][rg * 2 + 1] * xf.y;
                            d[mf][nj][rg * 2 + 0] = 0.f;
                            d[mf][nj][rg * 2 + 1] = 0.f;
                        }
                        acc[mf][rg] += sum;
                    }
                }
            }
        }
    }

    // ---- reduce: quad lanes, then across the 4 wn2 groups via smem ----
    #pragma unroll
    for (int mf = 0; mf < 2; ++mf)
        #pragma unroll
        for (int rg = 0; rg < 2; ++rg) {
            acc[mf][rg] += __shfl_xor_sync(0xffffffffu, acc[mf][rg], 1);
            acc[mf][rg] += __shfl_xor_sync(0xffffffffu, acc[mf][rg], 2);
        }

    float* red = reinterpret_cast<float*>(smem + SM_RED);
    if ((lane & 3) == 0) {
        #pragma unroll
        for (int mf = 0; mf < 2; ++mf)
            #pragma unroll
            for (int rg = 0; rg < 2; ++rg) {
                const int row = wm * 32 + mf * 16 + rg * 8 + ep_r;
                red[wn2 * BM + row] = acc[mf][rg];
            }
    }
    __syncthreads();
    if (tid < BM)
        out[r0 + tid] = red[tid] + red[BM + tid] +
                        red[2 * BM + tid] + red[3 * BM + tid];
}

extern "C" void kernel_launch(void* const* d_in, const int* in_sizes, int n_in,
                              void* d_out, int out_size) {
    const float* x = (const float*)d_in[0];
    const float* Q = (const float*)d_in[1];
    float* out     = (float*)d_out;

    const int B = in_sizes[0] / F_DIM;

    cudaFuncSetAttribute(bilinear_fp16_kernel,
                         cudaFuncAttributeMaxDynamicSharedMemorySize, SM_TOTAL);

    prep_frags_kernel<<<(NIT * 1024) / 256, 256>>>(Q);
    bilinear_fp16_kernel<<<B / BM, NTHREADS, SM_TOTAL>>>(x, out);
}